// round 4
// baseline (speedup 1.0000x reference)
#include <cuda_runtime.h>
#include <cstdint>

// ----------------------------------------------------------------------------
// Walsh-Hadamard transform, N = 2^25 floats.
// 25 butterfly stages split as 13 (pass 1, low bits) + 12 (pass 2, high bits).
// All stages commute, so grouping/order is free.
// ----------------------------------------------------------------------------

// ---------- packed f32x2 helpers ----------
__device__ __forceinline__ unsigned long long pack2(float x, float y) {
    unsigned long long u;
    asm("mov.b64 %0, {%1, %2};" : "=l"(u) : "f"(x), "f"(y));
    return u;
}
__device__ __forceinline__ void unpack2(unsigned long long u, float &x, float &y) {
    asm("mov.b64 {%0, %1}, %2;" : "=f"(x), "=f"(y) : "l"(u));
}
__device__ __forceinline__ unsigned long long add2(unsigned long long a, unsigned long long b) {
    unsigned long long r;
    asm("add.rn.f32x2 %0, %1, %2;" : "=l"(r) : "l"(a), "l"(b));
    return r;
}
__device__ __forceinline__ unsigned long long fma2(unsigned long long a, unsigned long long b,
                                                   unsigned long long c) {
    unsigned long long r;
    asm("fma.rn.f32x2 %0, %1, %2, %3;" : "=l"(r) : "l"(a), "l"(b), "l"(c));
    return r;
}

// Packed butterfly between two f32x2 registers: a <- a+b ; b <- a-b.
// a-b computed as fma(b, -2, a+b) = (a+b) - 2b (avoids sub.f32x2).
__device__ __forceinline__ void bflyp(unsigned long long &a, unsigned long long &b,
                                      unsigned long long NEG2) {
    unsigned long long s = add2(a, b);
    b = fma2(b, NEG2, s);
    a = s;
}

// Butterfly between the two lanes inside one f32x2 (scalar).
__device__ __forceinline__ unsigned long long bflyin(unsigned long long a) {
    float x, y;
    unpack2(a, x, y);
    return pack2(x + y, x - y);
}

// Shuffle-based butterfly: partner = lane ^ mask, result = self*sgn + other.
// sgn = +1 on the low side (-> a+b), -1 on the high side (-> a-b).
__device__ __forceinline__ unsigned long long shflb(unsigned long long v, int mask,
                                                    unsigned long long S) {
    unsigned long long o = __shfl_xor_sync(0xffffffffu, v, mask);
    return fma2(v, S, o);
}

// ----------------------------------------------------------------------------
// Pass 1: butterflies on element bits 0..12.  One block = 8192 contiguous
// floats.  Phase A does bits {0,1,10,11,12} (register resident, float4 loads),
// one smem round trip, phase B does bits {5..9} in registers and {2..4} via
// warp shuffles.  All smem access patterns hit 32 distinct banks per warp.
// ----------------------------------------------------------------------------
__global__ void __launch_bounds__(256) wht_pass1(const float* __restrict__ x,
                                                 float* __restrict__ y) {
    __shared__ __align__(16) float s[8192];
    const int tid  = threadIdx.x;       // 0..255
    const int lane = tid & 31;
    const long long base = (long long)blockIdx.x << 13;
    const unsigned long long NEG2 = pack2(-2.f, -2.f);

    unsigned long long v[16];

    // ---- Phase A: element e = 4*tid + 1024*jj + k ----
    // v[2*jj]   holds (k=0, k=1), v[2*jj+1] holds (k=2, k=3)
#pragma unroll
    for (int jj = 0; jj < 8; ++jj) {
        float4 f = *reinterpret_cast<const float4*>(x + base + 4 * tid + 1024 * jj);
        v[2 * jj]     = pack2(f.x, f.y);
        v[2 * jj + 1] = pack2(f.z, f.w);
    }
    // bit 0 (k bit 0 = inside each f32x2)
#pragma unroll
    for (int i = 0; i < 16; ++i) v[i] = bflyin(v[i]);
    // bit 1 (k bit 1)
#pragma unroll
    for (int jj = 0; jj < 8; ++jj) bflyp(v[2 * jj], v[2 * jj + 1], NEG2);
    // bit 10 (jj ^ 1)
#pragma unroll
    for (int jj = 0; jj < 8; jj += 2) {
        bflyp(v[2 * jj],     v[2 * jj + 2], NEG2);
        bflyp(v[2 * jj + 1], v[2 * jj + 3], NEG2);
    }
    // bit 11 (jj ^ 2)
#pragma unroll
    for (int g = 0; g < 8; g += 4) {
#pragma unroll
        for (int jj = g; jj < g + 2; ++jj) {
            bflyp(v[2 * jj],     v[2 * jj + 4], NEG2);
            bflyp(v[2 * jj + 1], v[2 * jj + 5], NEG2);
        }
    }
    // bit 12 (jj ^ 4)
#pragma unroll
    for (int jj = 0; jj < 4; ++jj) {
        bflyp(v[2 * jj],     v[2 * jj + 8], NEG2);
        bflyp(v[2 * jj + 1], v[2 * jj + 9], NEG2);
    }
    // store to smem (STS.128, lane-consecutive -> conflict free)
#pragma unroll
    for (int jj = 0; jj < 8; ++jj) {
        float a, b, c, d;
        unpack2(v[2 * jj], a, b);
        unpack2(v[2 * jj + 1], c, d);
        *reinterpret_cast<float4*>(s + 4 * tid + 1024 * jj) = make_float4(a, b, c, d);
    }
    __syncthreads();

    // ---- Phase B: e = q | (rr<<2) | (j<<5) | (w<<10) ----
    //   q = lane bits 3..4 -> e bits 0..1 ; rr = lane bits 0..2 -> e bits 2..4
    //   w = tid>>5 -> e bits 10..12 ; j (register, 5 bits) -> e bits 5..9
    // Per warp, fixed j: 32 consecutive elements -> conflict-free LDS,
    // 128B-contiguous global stores.
    const int eb = ((lane >> 3) & 3) | ((lane & 7) << 2) | ((tid >> 5) << 10);
#pragma unroll
    for (int i = 0; i < 16; ++i)
        v[i] = pack2(s[eb + 32 * i], s[eb + 32 * (i + 16)]);   // pack dim = e bit 9
    // bit 5 (j ^ 1)
#pragma unroll
    for (int i = 0; i < 16; i += 2) bflyp(v[i], v[i + 1], NEG2);
    // bit 6 (j ^ 2)
#pragma unroll
    for (int i = 0; i < 16; i += 4) {
        bflyp(v[i],     v[i + 2], NEG2);
        bflyp(v[i + 1], v[i + 3], NEG2);
    }
    // bit 7 (j ^ 4)
#pragma unroll
    for (int g = 0; g < 16; g += 8) {
#pragma unroll
        for (int i = g; i < g + 4; ++i) bflyp(v[i], v[i + 4], NEG2);
    }
    // bit 8 (j ^ 8)
#pragma unroll
    for (int i = 0; i < 8; ++i) bflyp(v[i], v[i + 8], NEG2);
    // bit 9 (pack dim)
#pragma unroll
    for (int i = 0; i < 16; ++i) v[i] = bflyin(v[i]);
    // bits 2..4 via shfl_xor 1,2,4 (lane bits 0..2)
#pragma unroll
    for (int m = 0; m < 3; ++m) {
        const int mask = 1 << m;
        const float sg = (lane & mask) ? -1.f : 1.f;
        const unsigned long long S = pack2(sg, sg);
#pragma unroll
        for (int i = 0; i < 16; ++i) v[i] = shflb(v[i], mask, S);
    }
    // store (per warp, fixed j: 128B contiguous)
#pragma unroll
    for (int i = 0; i < 16; ++i) {
        float a, b;
        unpack2(v[i], a, b);
        y[base + eb + 32 * i]        = a;
        y[base + eb + 32 * (i + 16)] = b;
    }
}

// ----------------------------------------------------------------------------
// Pass 2: butterflies on element bits 13..24.  View data as [4096 rows x 8192
// cols] (row = e>>13).  One block owns 8 columns x all 4096 rows (128KB smem).
// Phase A: row bits 7..11 ; phase B: row bits 2..6 (regs) + 0..1 (shfl).
// Global traffic is 4 x 32B full sectors per warp instruction.  In-place.
// ----------------------------------------------------------------------------
__global__ void __launch_bounds__(1024, 1) wht_pass2(float* __restrict__ y) {
    extern __shared__ float t[];                 // 32768 floats = 128 KB
    const int tid  = threadIdx.x;                // 0..1023
    const int lane = tid & 31;
    const int c    = tid & 7;                    // column within the 8-col tile
    const long long cb = (long long)blockIdx.x * 8 + c;
    const unsigned long long NEG2 = pack2(-2.f, -2.f);

    unsigned long long v[16];

    // ---- Phase A: r = rl + 128*j, rl = tid>>3 ----
    const int rl = tid >> 3;
    {
        const float* src = y + cb + (long long)rl * 8192;
#pragma unroll
        for (int i = 0; i < 16; ++i) {
            float a = src[(long long)(128 * i) * 8192];
            float b = src[(long long)(128 * (i + 16)) * 8192];
            v[i] = pack2(a, b);                  // pack dim = row bit 11
        }
    }
    // row bit 7 (j ^ 1)
#pragma unroll
    for (int i = 0; i < 16; i += 2) bflyp(v[i], v[i + 1], NEG2);
    // row bit 8 (j ^ 2)
#pragma unroll
    for (int i = 0; i < 16; i += 4) {
        bflyp(v[i],     v[i + 2], NEG2);
        bflyp(v[i + 1], v[i + 3], NEG2);
    }
    // row bit 9 (j ^ 4)
#pragma unroll
    for (int g = 0; g < 16; g += 8) {
#pragma unroll
        for (int i = g; i < g + 4; ++i) bflyp(v[i], v[i + 4], NEG2);
    }
    // row bit 10 (j ^ 8)
#pragma unroll
    for (int i = 0; i < 8; ++i) bflyp(v[i], v[i + 8], NEG2);
    // row bit 11 (pack dim)
#pragma unroll
    for (int i = 0; i < 16; ++i) v[i] = bflyin(v[i]);
    // store smem: idx = r*8 + c  (per warp: 32 distinct banks)
#pragma unroll
    for (int i = 0; i < 16; ++i) {
        float a, b;
        unpack2(v[i], a, b);
        t[(rl + 128 * i) * 8 + c]        = a;
        t[(rl + 128 * (i + 16)) * 8 + c] = b;
    }
    __syncthreads();

    // ---- Phase B: r = q + 4*j + 128*w ----
    //   q = lane bits 3..4 -> row bits 0..1 ; w = tid>>5 -> row bits 7..11
    const int q  = (lane >> 3) & 3;
    const int w  = tid >> 5;
    const int rb = q + 128 * w;
#pragma unroll
    for (int i = 0; i < 16; ++i)
        v[i] = pack2(t[(rb + 4 * i) * 8 + c],
                     t[(rb + 4 * (i + 16)) * 8 + c]);   // pack dim = row bit 6
    // row bit 2 (j ^ 1)
#pragma unroll
    for (int i = 0; i < 16; i += 2) bflyp(v[i], v[i + 1], NEG2);
    // row bit 3 (j ^ 2)
#pragma unroll
    for (int i = 0; i < 16; i += 4) {
        bflyp(v[i],     v[i + 2], NEG2);
        bflyp(v[i + 1], v[i + 3], NEG2);
    }
    // row bit 4 (j ^ 4)
#pragma unroll
    for (int g = 0; g < 16; g += 8) {
#pragma unroll
        for (int i = g; i < g + 4; ++i) bflyp(v[i], v[i + 4], NEG2);
    }
    // row bit 5 (j ^ 8)
#pragma unroll
    for (int i = 0; i < 8; ++i) bflyp(v[i], v[i + 8], NEG2);
    // row bit 6 (pack dim)
#pragma unroll
    for (int i = 0; i < 16; ++i) v[i] = bflyin(v[i]);
    // row bits 0,1 via shfl_xor 8,16 (lane bits 3,4)
#pragma unroll
    for (int m = 0; m < 2; ++m) {
        const int mask = 8 << m;
        const float sg = (lane & mask) ? -1.f : 1.f;
        const unsigned long long S = pack2(sg, sg);
#pragma unroll
        for (int i = 0; i < 16; ++i) v[i] = shflb(v[i], mask, S);
    }
    // store global (fixed j: 4 rows x 32B full sectors per warp instr)
    float* dst = y + cb;
#pragma unroll
    for (int i = 0; i < 16; ++i) {
        float a, b;
        unpack2(v[i], a, b);
        dst[(long long)(rb + 4 * i) * 8192]        = a;
        dst[(long long)(rb + 4 * (i + 16)) * 8192] = b;
    }
}

// ----------------------------------------------------------------------------
extern "C" void kernel_launch(void* const* d_in, const int* in_sizes, int n_in,
                              void* d_out, int out_size) {
    (void)in_sizes; (void)n_in; (void)out_size;
    const float* x = (const float*)d_in[0];
    float* y = (float*)d_out;

    // 128 KB dynamic smem for pass 2 (idempotent, not a stream op -> capture-safe)
    cudaFuncSetAttribute(wht_pass2, cudaFuncAttributeMaxDynamicSharedMemorySize, 131072);

    // Pass 1: bits 0..12, 2^25 / 2^13 = 4096 blocks
    wht_pass1<<<4096, 256>>>(x, y);
    // Pass 2: bits 13..24, 8192 cols / 8 per block = 1024 blocks
    wht_pass2<<<1024, 1024, 131072>>>(y);
}

// round 9
// speedup vs baseline: 1.0404x; 1.0404x over previous
#include <cuda_runtime.h>
#include <cstdint>

// ----------------------------------------------------------------------------
// Walsh-Hadamard transform, N = 2^25 floats.
// Bit split: pass1 = element bits 0..13 (16K-float tiles), pass2 = bits 14..24
// (2048-row column transform). Both kernels: 512 threads, 64 KB dynamic smem,
// __launch_bounds__(512,2) -> 2 blocks/SM for barrier/wave overlap.
//
// Stage coverage audit (each bit exactly once):
//   pass1 phase A: {0,1} (in-reg) + {11,12,13} (jj) + {5} (shfl m8)
//   pass1 phase B: {6,7,8,9} (i-pairs) + {10} (pack) + {2,3,4} (shfl m4,8,16)
//   pass2 phase A: {6,7,8,9} (i-pairs) + {10} (pack)          [row bits]
//   pass2 phase B: {2,3,4,5} (i-pairs) + {0,1} (shfl m8,16)   [row bits]
//     NOTE: phase B pack dim (row bit 6) is ADDRESSING ONLY - no butterfly
//     (bit 6 belongs to phase A; double-applying it was the R4 bug).
// ----------------------------------------------------------------------------

// ---------- packed f32x2 helpers ----------
__device__ __forceinline__ unsigned long long pack2(float x, float y) {
    unsigned long long u;
    asm("mov.b64 %0, {%1, %2};" : "=l"(u) : "f"(x), "f"(y));
    return u;
}
__device__ __forceinline__ void unpack2(unsigned long long u, float &x, float &y) {
    asm("mov.b64 {%0, %1}, %2;" : "=f"(x), "=f"(y) : "l"(u));
}
__device__ __forceinline__ unsigned long long add2(unsigned long long a, unsigned long long b) {
    unsigned long long r;
    asm("add.rn.f32x2 %0, %1, %2;" : "=l"(r) : "l"(a), "l"(b));
    return r;
}
__device__ __forceinline__ unsigned long long fma2(unsigned long long a, unsigned long long b,
                                                   unsigned long long c) {
    unsigned long long r;
    asm("fma.rn.f32x2 %0, %1, %2, %3;" : "=l"(r) : "l"(a), "l"(b), "l"(c));
    return r;
}

// a <- a+b ; b <- a-b  (a-b = fma(b,-2,a+b))
__device__ __forceinline__ void bflyp(unsigned long long &a, unsigned long long &b,
                                      unsigned long long NEG2) {
    unsigned long long s = add2(a, b);
    b = fma2(b, NEG2, s);
    a = s;
}
// butterfly inside one f32x2
__device__ __forceinline__ unsigned long long bflyin(unsigned long long a) {
    float x, y;
    unpack2(a, x, y);
    return pack2(x + y, x - y);
}
// shuffle butterfly: result = self*S + partner(lane^mask)
__device__ __forceinline__ unsigned long long shflb(unsigned long long v, int mask,
                                                    unsigned long long S) {
    unsigned long long o = __shfl_xor_sync(0xffffffffu, v, mask);
    return fma2(v, S, o);
}

// ----------------------------------------------------------------------------
// Pass 1: bits 0..13.  Block = 16384 consecutive floats, 512 threads, 64 KB.
// Phase A: e = k + 4*tid + 2048*jj  (k = bits 0,1 ; lane -> bits 2..6 ;
//   w=tid>>5 -> bits 7..10 ; jj -> bits 11..13).  float4 loads, bits
//   {0,1,11,12,13} in regs, bit 5 via shfl mask 8 (lane bit 3).
// Phase B: e = lane + 32*(w&1) + 64*i (+1024 pack) + 2048*(w>>1).
//   bits {6..9} i-pairs, {10} pack, {2,3,4} shfl.  Per warp, fixed i:
//   32 consecutive elements -> conflict-free LDS, 128B-contiguous stores.
// ----------------------------------------------------------------------------
__global__ void __launch_bounds__(512, 2) wht_pass1(const float* __restrict__ x,
                                                    float* __restrict__ y) {
    extern __shared__ __align__(16) float s[];          // 16384 floats = 64 KB
    const int tid  = threadIdx.x;                       // 0..511
    const int lane = tid & 31;
    const int base = blockIdx.x << 14;
    const unsigned long long NEG2 = pack2(-2.f, -2.f);

    unsigned long long v[16];

    // ---- Phase A ----
#pragma unroll
    for (int jj = 0; jj < 8; ++jj) {
        float4 f = *reinterpret_cast<const float4*>(x + base + 4 * tid + 2048 * jj);
        v[2 * jj]     = pack2(f.x, f.y);
        v[2 * jj + 1] = pack2(f.z, f.w);
    }
    // bit 0 (k bit 0, inside f32x2)
#pragma unroll
    for (int i = 0; i < 16; ++i) v[i] = bflyin(v[i]);
    // bit 1 (k bit 1)
#pragma unroll
    for (int jj = 0; jj < 8; ++jj) bflyp(v[2 * jj], v[2 * jj + 1], NEG2);
    // bit 11 (jj ^ 1)
#pragma unroll
    for (int jj = 0; jj < 8; jj += 2) {
        bflyp(v[2 * jj],     v[2 * jj + 2], NEG2);
        bflyp(v[2 * jj + 1], v[2 * jj + 3], NEG2);
    }
    // bit 12 (jj ^ 2)
#pragma unroll
    for (int g = 0; g < 8; g += 4)
#pragma unroll
        for (int jj = g; jj < g + 2; ++jj) {
            bflyp(v[2 * jj],     v[2 * jj + 4], NEG2);
            bflyp(v[2 * jj + 1], v[2 * jj + 5], NEG2);
        }
    // bit 13 (jj ^ 4)
#pragma unroll
    for (int jj = 0; jj < 4; ++jj) {
        bflyp(v[2 * jj],     v[2 * jj + 8], NEG2);
        bflyp(v[2 * jj + 1], v[2 * jj + 9], NEG2);
    }
    // bit 5 via shfl mask 8 (lane bit 3 -> e bit 5)
    {
        const float sg = (lane & 8) ? -1.f : 1.f;
        const unsigned long long S = pack2(sg, sg);
#pragma unroll
        for (int i = 0; i < 16; ++i) v[i] = shflb(v[i], 8, S);
    }
    // store (512B contiguous per warp)
#pragma unroll
    for (int jj = 0; jj < 8; ++jj) {
        float a, b, c, d;
        unpack2(v[2 * jj], a, b);
        unpack2(v[2 * jj + 1], c, d);
        *reinterpret_cast<float4*>(s + 4 * tid + 2048 * jj) = make_float4(a, b, c, d);
    }
    __syncthreads();

    // ---- Phase B ----
    const int w  = tid >> 5;
    const int eA = lane + 32 * (w & 1) + 2048 * (w >> 1);
#pragma unroll
    for (int i = 0; i < 16; ++i)
        v[i] = pack2(s[eA + 64 * i], s[eA + 64 * i + 1024]);   // pack dim = e bit 10
    // bit 6 (i ^ 1)
#pragma unroll
    for (int i = 0; i < 16; i += 2) bflyp(v[i], v[i + 1], NEG2);
    // bit 7 (i ^ 2)
#pragma unroll
    for (int i = 0; i < 16; i += 4) {
        bflyp(v[i],     v[i + 2], NEG2);
        bflyp(v[i + 1], v[i + 3], NEG2);
    }
    // bit 8 (i ^ 4)
#pragma unroll
    for (int g = 0; g < 16; g += 8)
#pragma unroll
        for (int i = g; i < g + 4; ++i) bflyp(v[i], v[i + 4], NEG2);
    // bit 9 (i ^ 8)
#pragma unroll
    for (int i = 0; i < 8; ++i) bflyp(v[i], v[i + 8], NEG2);
    // bit 10 (pack dim)
#pragma unroll
    for (int i = 0; i < 16; ++i) v[i] = bflyin(v[i]);
    // bits 2,3,4 via shfl masks 4,8,16 (lane bits 2..4)
#pragma unroll
    for (int m = 0; m < 3; ++m) {
        const int mask = 4 << m;
        const float sg = (lane & mask) ? -1.f : 1.f;
        const unsigned long long S = pack2(sg, sg);
#pragma unroll
        for (int i = 0; i < 16; ++i) v[i] = shflb(v[i], mask, S);
    }
    // store (128B contiguous per warp per instr)
#pragma unroll
    for (int i = 0; i < 16; ++i) {
        float a, b;
        unpack2(v[i], a, b);
        y[base + eA + 64 * i]        = a;
        y[base + eA + 64 * i + 1024] = b;
    }
}

// ----------------------------------------------------------------------------
// Pass 2: bits 14..24.  View as [2048 rows x 16384 cols]; block owns 8 cols x
// all 2048 rows = 64 KB smem, 512 threads, in-place.
// Phase A: r = rl + 64*i (+1024 pack); butterflies on row bits {6..9} + {10}.
// Phase B: r = q + 4*i (+64 pack) + 128*w; butterflies on {2..5} + {0,1 shfl}.
//   Pack dim (row bit 6) in phase B is addressing only - NO butterfly.
// Global traffic: 4 full 32B sectors per warp instruction both phases.
// ----------------------------------------------------------------------------
__global__ void __launch_bounds__(512, 2) wht_pass2(float* __restrict__ y) {
    extern __shared__ float t[];                 // 16384 floats = 64 KB
    const int tid  = threadIdx.x;                // 0..511
    const int lane = tid & 31;
    const int c    = tid & 7;                    // column within 8-col tile
    const int cb   = blockIdx.x * 8 + c;
    const unsigned long long NEG2 = pack2(-2.f, -2.f);

    unsigned long long v[16];

    // ---- Phase A: r = rl + 64*j, rl = tid>>3 in [0,64) ----
    const int rl = tid >> 3;
    {
        const float* src = y + cb + rl * 16384;
#pragma unroll
        for (int i = 0; i < 16; ++i) {
            float a = src[(64 * i) * 16384];
            float b = src[(64 * (i + 16)) * 16384];
            v[i] = pack2(a, b);                  // pack dim = row bit 10
        }
    }
    // row bit 6 (i ^ 1)
#pragma unroll
    for (int i = 0; i < 16; i += 2) bflyp(v[i], v[i + 1], NEG2);
    // row bit 7 (i ^ 2)
#pragma unroll
    for (int i = 0; i < 16; i += 4) {
        bflyp(v[i],     v[i + 2], NEG2);
        bflyp(v[i + 1], v[i + 3], NEG2);
    }
    // row bit 8 (i ^ 4)
#pragma unroll
    for (int g = 0; g < 16; g += 8)
#pragma unroll
        for (int i = g; i < g + 4; ++i) bflyp(v[i], v[i + 4], NEG2);
    // row bit 9 (i ^ 8)
#pragma unroll
    for (int i = 0; i < 8; ++i) bflyp(v[i], v[i + 8], NEG2);
    // row bit 10 (pack dim)
#pragma unroll
    for (int i = 0; i < 16; ++i) v[i] = bflyin(v[i]);
    // smem store: 32 consecutive words per warp -> conflict-free
#pragma unroll
    for (int i = 0; i < 16; ++i) {
        float a, b;
        unpack2(v[i], a, b);
        t[(rl + 64 * i) * 8 + c]        = a;
        t[(rl + 64 * (i + 16)) * 8 + c] = b;
    }
    __syncthreads();

    // ---- Phase B: r = q + 4*j (+64 pack) + 128*w ----
    const int q  = (lane >> 3) & 3;              // row bits 0,1
    const int w  = tid >> 5;                     // row bits 7..10
    const int rb = q + 128 * w;
#pragma unroll
    for (int i = 0; i < 16; ++i)
        v[i] = pack2(t[(rb + 4 * i) * 8 + c],
                     t[(rb + 4 * (i + 16)) * 8 + c]);   // pack dim = row bit 6
    // row bit 2 (i ^ 1)
#pragma unroll
    for (int i = 0; i < 16; i += 2) bflyp(v[i], v[i + 1], NEG2);
    // row bit 3 (i ^ 2)
#pragma unroll
    for (int i = 0; i < 16; i += 4) {
        bflyp(v[i],     v[i + 2], NEG2);
        bflyp(v[i + 1], v[i + 3], NEG2);
    }
    // row bit 4 (i ^ 4)
#pragma unroll
    for (int g = 0; g < 16; g += 8)
#pragma unroll
        for (int i = g; i < g + 4; ++i) bflyp(v[i], v[i + 4], NEG2);
    // row bit 5 (i ^ 8)
#pragma unroll
    for (int i = 0; i < 8; ++i) bflyp(v[i], v[i + 8], NEG2);
    // (pack dim = row bit 6: NO butterfly here - done in phase A)
    // row bits 0,1 via shfl masks 8,16 (lane bits 3,4)
#pragma unroll
    for (int m = 0; m < 2; ++m) {
        const int mask = 8 << m;
        const float sg = (lane & mask) ? -1.f : 1.f;
        const unsigned long long S = pack2(sg, sg);
#pragma unroll
        for (int i = 0; i < 16; ++i) v[i] = shflb(v[i], mask, S);
    }
    // global store: 4 rows x 32B full sectors per warp instruction
    float* dst = y + cb;
#pragma unroll
    for (int i = 0; i < 16; ++i) {
        float a, b;
        unpack2(v[i], a, b);
        dst[(rb + 4 * i) * 16384]        = a;
        dst[(rb + 4 * (i + 16)) * 16384] = b;
    }
}

// ----------------------------------------------------------------------------
extern "C" void kernel_launch(void* const* d_in, const int* in_sizes, int n_in,
                              void* d_out, int out_size) {
    (void)in_sizes; (void)n_in; (void)out_size;
    const float* x = (const float*)d_in[0];
    float* y = (float*)d_out;

    // 64 KB dynamic smem for both kernels (idempotent, capture-safe)
    cudaFuncSetAttribute(wht_pass1, cudaFuncAttributeMaxDynamicSharedMemorySize, 65536);
    cudaFuncSetAttribute(wht_pass2, cudaFuncAttributeMaxDynamicSharedMemorySize, 65536);

    // Pass 1: bits 0..13, 2^25 / 2^14 = 2048 blocks
    wht_pass1<<<2048, 512, 65536>>>(x, y);
    // Pass 2: bits 14..24, 16384 cols / 8 per block = 2048 blocks
    wht_pass2<<<2048, 512, 65536>>>(y);
}

// round 10
// speedup vs baseline: 1.1087x; 1.0656x over previous
#include <cuda.h>
#include <cuda_runtime.h>
#include <cstdint>

// ----------------------------------------------------------------------------
// Walsh-Hadamard transform, N = 2^25 floats.
// pass1: element bits 0..13 (16K-float contiguous tiles)  [unchanged from R7]
// pass2: element bits 14..24 as a 2048-row x 16384-col column transform.
//   R9 change: global traffic via TMA (cp.async.bulk.tensor.2d) instead of
//   strided LDG/STG - the 8-col stripe makes every scalar warp access touch
//   4 lines at 32B each (4 l1tex wavefronts/instr); ncu showed l1tex 67.9%
//   as the binder.  TMA moves the same bytes on the L2<->SMEM path at LTS
//   cap, bypassing the wavefront bottleneck.  Butterfly structure and smem
//   layout are identical to the proven R7 kernel.
// Fallback: if driver entry point / tensor map creation fails, launch the
//   R7 LDG-based pass2 (known correct, 107us total).
// ----------------------------------------------------------------------------

// ---------- packed f32x2 helpers ----------
__device__ __forceinline__ unsigned long long pack2(float x, float y) {
    unsigned long long u;
    asm("mov.b64 %0, {%1, %2};" : "=l"(u) : "f"(x), "f"(y));
    return u;
}
__device__ __forceinline__ void unpack2(unsigned long long u, float &x, float &y) {
    asm("mov.b64 {%0, %1}, %2;" : "=f"(x), "=f"(y) : "l"(u));
}
__device__ __forceinline__ unsigned long long add2(unsigned long long a, unsigned long long b) {
    unsigned long long r;
    asm("add.rn.f32x2 %0, %1, %2;" : "=l"(r) : "l"(a), "l"(b));
    return r;
}
__device__ __forceinline__ unsigned long long fma2(unsigned long long a, unsigned long long b,
                                                   unsigned long long c) {
    unsigned long long r;
    asm("fma.rn.f32x2 %0, %1, %2, %3;" : "=l"(r) : "l"(a), "l"(b), "l"(c));
    return r;
}
// a <- a+b ; b <- a-b  (a-b = fma(b,-2,a+b))
__device__ __forceinline__ void bflyp(unsigned long long &a, unsigned long long &b,
                                      unsigned long long NEG2) {
    unsigned long long s = add2(a, b);
    b = fma2(b, NEG2, s);
    a = s;
}
__device__ __forceinline__ unsigned long long bflyin(unsigned long long a) {
    float x, y;
    unpack2(a, x, y);
    return pack2(x + y, x - y);
}
__device__ __forceinline__ unsigned long long shflb(unsigned long long v, int mask,
                                                    unsigned long long S) {
    unsigned long long o = __shfl_xor_sync(0xffffffffu, v, mask);
    return fma2(v, S, o);
}
__device__ __forceinline__ uint32_t smem_u32(const void* p) {
    uint32_t a;
    asm("{ .reg .u64 t; cvta.to.shared.u64 t, %1; cvt.u32.u64 %0, t; }" : "=r"(a) : "l"(p));
    return a;
}
__device__ __forceinline__ void mbar_wait(uint32_t addr, uint32_t parity) {
    asm volatile(
        "{\n\t.reg .pred P1;\n\t"
        "WL_%=:\n\t"
        "mbarrier.try_wait.parity.acquire.cta.shared::cta.b64 P1, [%0], %1, 0x989680;\n\t"
        "@P1 bra.uni WD_%=;\n\t"
        "bra.uni WL_%=;\n\t"
        "WD_%=:\n\t}"
        :: "r"(addr), "r"(parity) : "memory");
}

// ----------------------------------------------------------------------------
// Pass 1: bits 0..13 (unchanged from R7 - passing, fully coalesced)
// ----------------------------------------------------------------------------
__global__ void __launch_bounds__(512, 2) wht_pass1(const float* __restrict__ x,
                                                    float* __restrict__ y) {
    extern __shared__ __align__(16) float s[];          // 16384 floats = 64 KB
    const int tid  = threadIdx.x;
    const int lane = tid & 31;
    const int base = blockIdx.x << 14;
    const unsigned long long NEG2 = pack2(-2.f, -2.f);

    unsigned long long v[16];

    // ---- Phase A: bits {0,1} + {11,12,13} + {5 shfl} ----
#pragma unroll
    for (int jj = 0; jj < 8; ++jj) {
        float4 f = *reinterpret_cast<const float4*>(x + base + 4 * tid + 2048 * jj);
        v[2 * jj]     = pack2(f.x, f.y);
        v[2 * jj + 1] = pack2(f.z, f.w);
    }
#pragma unroll
    for (int i = 0; i < 16; ++i) v[i] = bflyin(v[i]);                       // bit 0
#pragma unroll
    for (int jj = 0; jj < 8; ++jj) bflyp(v[2 * jj], v[2 * jj + 1], NEG2);   // bit 1
#pragma unroll
    for (int jj = 0; jj < 8; jj += 2) {                                     // bit 11
        bflyp(v[2 * jj],     v[2 * jj + 2], NEG2);
        bflyp(v[2 * jj + 1], v[2 * jj + 3], NEG2);
    }
#pragma unroll
    for (int g = 0; g < 8; g += 4)                                          // bit 12
#pragma unroll
        for (int jj = g; jj < g + 2; ++jj) {
            bflyp(v[2 * jj],     v[2 * jj + 4], NEG2);
            bflyp(v[2 * jj + 1], v[2 * jj + 5], NEG2);
        }
#pragma unroll
    for (int jj = 0; jj < 4; ++jj) {                                        // bit 13
        bflyp(v[2 * jj],     v[2 * jj + 8], NEG2);
        bflyp(v[2 * jj + 1], v[2 * jj + 9], NEG2);
    }
    {                                                                       // bit 5
        const float sg = (lane & 8) ? -1.f : 1.f;
        const unsigned long long S = pack2(sg, sg);
#pragma unroll
        for (int i = 0; i < 16; ++i) v[i] = shflb(v[i], 8, S);
    }
#pragma unroll
    for (int jj = 0; jj < 8; ++jj) {
        float a, b, c, d;
        unpack2(v[2 * jj], a, b);
        unpack2(v[2 * jj + 1], c, d);
        *reinterpret_cast<float4*>(s + 4 * tid + 2048 * jj) = make_float4(a, b, c, d);
    }
    __syncthreads();

    // ---- Phase B: bits {6..9} + {10 pack} + {2,3,4 shfl} ----
    const int w  = tid >> 5;
    const int eA = lane + 32 * (w & 1) + 2048 * (w >> 1);
#pragma unroll
    for (int i = 0; i < 16; ++i)
        v[i] = pack2(s[eA + 64 * i], s[eA + 64 * i + 1024]);
#pragma unroll
    for (int i = 0; i < 16; i += 2) bflyp(v[i], v[i + 1], NEG2);            // bit 6
#pragma unroll
    for (int i = 0; i < 16; i += 4) {                                       // bit 7
        bflyp(v[i],     v[i + 2], NEG2);
        bflyp(v[i + 1], v[i + 3], NEG2);
    }
#pragma unroll
    for (int g = 0; g < 16; g += 8)                                         // bit 8
#pragma unroll
        for (int i = g; i < g + 4; ++i) bflyp(v[i], v[i + 4], NEG2);
#pragma unroll
    for (int i = 0; i < 8; ++i) bflyp(v[i], v[i + 8], NEG2);                // bit 9
#pragma unroll
    for (int i = 0; i < 16; ++i) v[i] = bflyin(v[i]);                       // bit 10
#pragma unroll
    for (int m = 0; m < 3; ++m) {                                           // bits 2..4
        const int mask = 4 << m;
        const float sg = (lane & mask) ? -1.f : 1.f;
        const unsigned long long S = pack2(sg, sg);
#pragma unroll
        for (int i = 0; i < 16; ++i) v[i] = shflb(v[i], mask, S);
    }
#pragma unroll
    for (int i = 0; i < 16; ++i) {
        float a, b;
        unpack2(v[i], a, b);
        y[base + eA + 64 * i]        = a;
        y[base + eA + 64 * i + 1024] = b;
    }
}

// ----------------------------------------------------------------------------
// Pass 2 (TMA): bits 14..24.  [2048 rows x 16384 cols], block = 8-col stripe.
// TMA in (8 boxes of 8x256) -> phase A (row bits 6..10, smem in-place) ->
// sync -> phase B (row bits 2..5 + 0,1 shfl, smem in-place) -> sync ->
// TMA out.  smem layout t[r*8+c] (no swizzle); all LDS/STS patterns are 32
// consecutive words per warp -> conflict-free.
// ----------------------------------------------------------------------------
__global__ void __launch_bounds__(512, 2) wht_pass2_tma(const __grid_constant__ CUtensorMap tmap) {
    extern __shared__ __align__(16) float t[];   // 16384 floats + mbarrier
    uint64_t* mbar = reinterpret_cast<uint64_t*>(t + 16384);
    const int tid  = threadIdx.x;
    const int lane = tid & 31;
    const int c    = tid & 7;
    const unsigned long long NEG2 = pack2(-2.f, -2.f);
    const uint32_t mb = smem_u32(mbar);
    const uint32_t ts = smem_u32(t);

    if (tid == 0)
        asm volatile("mbarrier.init.shared.b64 [%0], %1;" :: "r"(mb), "r"(1) : "memory");
    __syncthreads();

    if (tid == 0) {
        asm volatile("mbarrier.arrive.expect_tx.shared.b64 _, [%0], %1;"
                     :: "r"(mb), "r"(65536u) : "memory");
        const int cx = blockIdx.x * 8;
#pragma unroll
        for (int k = 0; k < 8; ++k) {
            asm volatile(
                "cp.async.bulk.tensor.2d.shared::cta.global.tile.mbarrier::complete_tx::bytes "
                "[%0], [%1, {%2, %3}], [%4];"
                :: "r"(ts + k * 8192), "l"(&tmap), "r"(cx), "r"(k * 256), "r"(mb)
                : "memory");
        }
    }
    mbar_wait(mb, 0);

    unsigned long long v[16];

    // ---- Phase A: rows r = rl + 64*i (+1024 pack); bits {6..9} + {10} ----
    const int rl = tid >> 3;                       // 0..63
#pragma unroll
    for (int i = 0; i < 16; ++i)
        v[i] = pack2(t[(rl + 64 * i) * 8 + c],
                     t[(rl + 64 * (i + 16)) * 8 + c]);
#pragma unroll
    for (int i = 0; i < 16; i += 2) bflyp(v[i], v[i + 1], NEG2);            // bit 6
#pragma unroll
    for (int i = 0; i < 16; i += 4) {                                       // bit 7
        bflyp(v[i],     v[i + 2], NEG2);
        bflyp(v[i + 1], v[i + 3], NEG2);
    }
#pragma unroll
    for (int g = 0; g < 16; g += 8)                                         // bit 8
#pragma unroll
        for (int i = g; i < g + 4; ++i) bflyp(v[i], v[i + 4], NEG2);
#pragma unroll
    for (int i = 0; i < 8; ++i) bflyp(v[i], v[i + 8], NEG2);                // bit 9
#pragma unroll
    for (int i = 0; i < 16; ++i) v[i] = bflyin(v[i]);                       // bit 10
    // write back to own addresses (each word owned by exactly one thread)
#pragma unroll
    for (int i = 0; i < 16; ++i) {
        float a, b;
        unpack2(v[i], a, b);
        t[(rl + 64 * i) * 8 + c]        = a;
        t[(rl + 64 * (i + 16)) * 8 + c] = b;
    }
    __syncthreads();

    // ---- Phase B: r = q + 4*i (+64 pack) + 128*w; bits {2..5} + {0,1 shfl} ----
    const int q  = (lane >> 3) & 3;
    const int w  = tid >> 5;
    const int rb = q + 128 * w;
#pragma unroll
    for (int i = 0; i < 16; ++i)
        v[i] = pack2(t[(rb + 4 * i) * 8 + c],
                     t[(rb + 4 * (i + 16)) * 8 + c]);   // pack dim = row bit 6 (passive)
#pragma unroll
    for (int i = 0; i < 16; i += 2) bflyp(v[i], v[i + 1], NEG2);            // bit 2
#pragma unroll
    for (int i = 0; i < 16; i += 4) {                                       // bit 3
        bflyp(v[i],     v[i + 2], NEG2);
        bflyp(v[i + 1], v[i + 3], NEG2);
    }
#pragma unroll
    for (int g = 0; g < 16; g += 8)                                         // bit 4
#pragma unroll
        for (int i = g; i < g + 4; ++i) bflyp(v[i], v[i + 4], NEG2);
#pragma unroll
    for (int i = 0; i < 8; ++i) bflyp(v[i], v[i + 8], NEG2);                // bit 5
#pragma unroll
    for (int m = 0; m < 2; ++m) {                                           // bits 0,1
        const int mask = 8 << m;
        const float sg = (lane & mask) ? -1.f : 1.f;
        const unsigned long long S = pack2(sg, sg);
#pragma unroll
        for (int i = 0; i < 16; ++i) v[i] = shflb(v[i], mask, S);
    }
    // results back to own addresses, then TMA store
#pragma unroll
    for (int i = 0; i < 16; ++i) {
        float a, b;
        unpack2(v[i], a, b);
        t[(rb + 4 * i) * 8 + c]        = a;
        t[(rb + 4 * (i + 16)) * 8 + c] = b;
    }
    __syncthreads();

    if (tid == 0) {
        asm volatile("fence.proxy.async.shared::cta;" ::: "memory");
        const int cx = blockIdx.x * 8;
#pragma unroll
        for (int k = 0; k < 8; ++k) {
            asm volatile(
                "cp.async.bulk.tensor.2d.global.shared::cta.tile.bulk_group "
                "[%0, {%1, %2}], [%3];"
                :: "l"(&tmap), "r"(cx), "r"(k * 256), "r"(ts + k * 8192)
                : "memory");
        }
        asm volatile("cp.async.bulk.commit_group;" ::: "memory");
        asm volatile("cp.async.bulk.wait_group 0;" ::: "memory");
    }
}

// ----------------------------------------------------------------------------
// Pass 2 (LDG fallback) - R7 kernel verbatim, known correct.
// ----------------------------------------------------------------------------
__global__ void __launch_bounds__(512, 2) wht_pass2_ldg(float* __restrict__ y) {
    extern __shared__ float t[];
    const int tid  = threadIdx.x;
    const int lane = tid & 31;
    const int c    = tid & 7;
    const int cb   = blockIdx.x * 8 + c;
    const unsigned long long NEG2 = pack2(-2.f, -2.f);

    unsigned long long v[16];

    const int rl = tid >> 3;
    {
        const float* src = y + cb + rl * 16384;
#pragma unroll
        for (int i = 0; i < 16; ++i) {
            float a = src[(64 * i) * 16384];
            float b = src[(64 * (i + 16)) * 16384];
            v[i] = pack2(a, b);
        }
    }
#pragma unroll
    for (int i = 0; i < 16; i += 2) bflyp(v[i], v[i + 1], NEG2);
#pragma unroll
    for (int i = 0; i < 16; i += 4) {
        bflyp(v[i],     v[i + 2], NEG2);
        bflyp(v[i + 1], v[i + 3], NEG2);
    }
#pragma unroll
    for (int g = 0; g < 16; g += 8)
#pragma unroll
        for (int i = g; i < g + 4; ++i) bflyp(v[i], v[i + 4], NEG2);
#pragma unroll
    for (int i = 0; i < 8; ++i) bflyp(v[i], v[i + 8], NEG2);
#pragma unroll
    for (int i = 0; i < 16; ++i) v[i] = bflyin(v[i]);
#pragma unroll
    for (int i = 0; i < 16; ++i) {
        float a, b;
        unpack2(v[i], a, b);
        t[(rl + 64 * i) * 8 + c]        = a;
        t[(rl + 64 * (i + 16)) * 8 + c] = b;
    }
    __syncthreads();

    const int q  = (lane >> 3) & 3;
    const int w  = tid >> 5;
    const int rb = q + 128 * w;
#pragma unroll
    for (int i = 0; i < 16; ++i)
        v[i] = pack2(t[(rb + 4 * i) * 8 + c],
                     t[(rb + 4 * (i + 16)) * 8 + c]);
#pragma unroll
    for (int i = 0; i < 16; i += 2) bflyp(v[i], v[i + 1], NEG2);
#pragma unroll
    for (int i = 0; i < 16; i += 4) {
        bflyp(v[i],     v[i + 2], NEG2);
        bflyp(v[i + 1], v[i + 3], NEG2);
    }
#pragma unroll
    for (int g = 0; g < 16; g += 8)
#pragma unroll
        for (int i = g; i < g + 4; ++i) bflyp(v[i], v[i + 4], NEG2);
#pragma unroll
    for (int i = 0; i < 8; ++i) bflyp(v[i], v[i + 8], NEG2);
#pragma unroll
    for (int m = 0; m < 2; ++m) {
        const int mask = 8 << m;
        const float sg = (lane & mask) ? -1.f : 1.f;
        const unsigned long long S = pack2(sg, sg);
#pragma unroll
        for (int i = 0; i < 16; ++i) v[i] = shflb(v[i], mask, S);
    }
    float* dst = y + cb;
#pragma unroll
    for (int i = 0; i < 16; ++i) {
        float a, b;
        unpack2(v[i], a, b);
        dst[(rb + 4 * i) * 16384]        = a;
        dst[(rb + 4 * (i + 16)) * 16384] = b;
    }
}

// ----------------------------------------------------------------------------
typedef CUresult (*PFN_encodeTiled)(
    CUtensorMap*, CUtensorMapDataType, cuuint32_t, void*,
    const cuuint64_t*, const cuuint64_t*, const cuuint32_t*, const cuuint32_t*,
    CUtensorMapInterleave, CUtensorMapSwizzle, CUtensorMapL2promotion,
    CUtensorMapFloatOOBfill);

extern "C" void kernel_launch(void* const* d_in, const int* in_sizes, int n_in,
                              void* d_out, int out_size) {
    (void)in_sizes; (void)n_in; (void)out_size;
    const float* x = (const float*)d_in[0];
    float* y = (float*)d_out;

    cudaFuncSetAttribute(wht_pass1,     cudaFuncAttributeMaxDynamicSharedMemorySize, 65536);
    cudaFuncSetAttribute(wht_pass2_tma, cudaFuncAttributeMaxDynamicSharedMemorySize, 65664);
    cudaFuncSetAttribute(wht_pass2_ldg, cudaFuncAttributeMaxDynamicSharedMemorySize, 65536);

    // Pass 1: bits 0..13
    wht_pass1<<<2048, 512, 65536>>>(x, y);

    // Build tensor map for pass 2 (runtime-resolved driver API; no -lcuda dep)
    bool tma_ok = false;
    CUtensorMap tmap;
    {
        void* fp = nullptr;
        cudaDriverEntryPointQueryResult qr = cudaDriverEntryPointSymbolNotFound;
        if (cudaGetDriverEntryPointByVersion("cuTensorMapEncodeTiled", &fp, 12000,
                                             cudaEnableDefault, &qr) == cudaSuccess &&
            qr == cudaDriverEntryPointSuccess && fp) {
            PFN_encodeTiled enc = (PFN_encodeTiled)fp;
            cuuint64_t dims[2]    = {16384, 2048};
            cuuint64_t strides[1] = {16384ull * 4ull};
            cuuint32_t box[2]     = {8, 256};
            cuuint32_t es[2]      = {1, 1};
            tma_ok = (enc(&tmap, CU_TENSOR_MAP_DATA_TYPE_FLOAT32, 2, y,
                          dims, strides, box, es,
                          CU_TENSOR_MAP_INTERLEAVE_NONE, CU_TENSOR_MAP_SWIZZLE_NONE,
                          CU_TENSOR_MAP_L2_PROMOTION_L2_128B,
                          CU_TENSOR_MAP_FLOAT_OOB_FILL_NONE) == CUDA_SUCCESS);
        }
    }

    // Pass 2: bits 14..24
    if (tma_ok)
        wht_pass2_tma<<<2048, 512, 65664>>>(tmap);
    else
        wht_pass2_ldg<<<2048, 512, 65536>>>(y);
}

// round 11
// speedup vs baseline: 1.1543x; 1.0411x over previous
#include <cuda.h>
#include <cuda_runtime.h>
#include <cstdint>

// ----------------------------------------------------------------------------
// Walsh-Hadamard transform, N = 2^25 floats.
// pass1: element bits 0..13 (16K-float contiguous tiles)    [R7, unchanged]
// pass2: element bits 14..24 as 2048-row x 16384-col column transform.
//   R10: persistent kernel, grid = #SMs, 3 x 64KB smem buffers, TMA load of
//   stripe k+1 issued before compute of stripe k, stores fire-and-forget in
//   a bulk group (completion enforced lazily via wait_group 1 before buffer
//   reuse).  Keeps the DMA engine streaming through compute and barriers.
// Fallback: R7 LDG pass2 if tensor-map creation fails.
// ----------------------------------------------------------------------------

// ---------- packed f32x2 helpers ----------
__device__ __forceinline__ unsigned long long pack2(float x, float y) {
    unsigned long long u;
    asm("mov.b64 %0, {%1, %2};" : "=l"(u) : "f"(x), "f"(y));
    return u;
}
__device__ __forceinline__ void unpack2(unsigned long long u, float &x, float &y) {
    asm("mov.b64 {%0, %1}, %2;" : "=f"(x), "=f"(y) : "l"(u));
}
__device__ __forceinline__ unsigned long long add2(unsigned long long a, unsigned long long b) {
    unsigned long long r;
    asm("add.rn.f32x2 %0, %1, %2;" : "=l"(r) : "l"(a), "l"(b));
    return r;
}
__device__ __forceinline__ unsigned long long fma2(unsigned long long a, unsigned long long b,
                                                   unsigned long long c) {
    unsigned long long r;
    asm("fma.rn.f32x2 %0, %1, %2, %3;" : "=l"(r) : "l"(a), "l"(b), "l"(c));
    return r;
}
// a <- a+b ; b <- a-b
__device__ __forceinline__ void bflyp(unsigned long long &a, unsigned long long &b,
                                      unsigned long long NEG2) {
    unsigned long long s = add2(a, b);
    b = fma2(b, NEG2, s);
    a = s;
}
__device__ __forceinline__ unsigned long long bflyin(unsigned long long a) {
    float x, y;
    unpack2(a, x, y);
    return pack2(x + y, x - y);
}
__device__ __forceinline__ unsigned long long shflb(unsigned long long v, int mask,
                                                    unsigned long long S) {
    unsigned long long o = __shfl_xor_sync(0xffffffffu, v, mask);
    return fma2(v, S, o);
}
__device__ __forceinline__ uint32_t smem_u32(const void* p) {
    uint32_t a;
    asm("{ .reg .u64 t; cvta.to.shared.u64 t, %1; cvt.u32.u64 %0, t; }" : "=r"(a) : "l"(p));
    return a;
}
__device__ __forceinline__ void mbar_wait(uint32_t addr, uint32_t parity) {
    asm volatile(
        "{\n\t.reg .pred P1;\n\t"
        "WL_%=:\n\t"
        "mbarrier.try_wait.parity.acquire.cta.shared::cta.b64 P1, [%0], %1, 0x989680;\n\t"
        "@P1 bra.uni WD_%=;\n\t"
        "bra.uni WL_%=;\n\t"
        "WD_%=:\n\t}"
        :: "r"(addr), "r"(parity) : "memory");
}

// ----------------------------------------------------------------------------
// Pass 1: bits 0..13 (unchanged, passing, fully coalesced)
// ----------------------------------------------------------------------------
__global__ void __launch_bounds__(512, 2) wht_pass1(const float* __restrict__ x,
                                                    float* __restrict__ y) {
    extern __shared__ __align__(16) float s[];          // 16384 floats = 64 KB
    const int tid  = threadIdx.x;
    const int lane = tid & 31;
    const int base = blockIdx.x << 14;
    const unsigned long long NEG2 = pack2(-2.f, -2.f);

    unsigned long long v[16];

    // ---- Phase A: bits {0,1} + {11,12,13} + {5 shfl} ----
#pragma unroll
    for (int jj = 0; jj < 8; ++jj) {
        float4 f = *reinterpret_cast<const float4*>(x + base + 4 * tid + 2048 * jj);
        v[2 * jj]     = pack2(f.x, f.y);
        v[2 * jj + 1] = pack2(f.z, f.w);
    }
#pragma unroll
    for (int i = 0; i < 16; ++i) v[i] = bflyin(v[i]);                       // bit 0
#pragma unroll
    for (int jj = 0; jj < 8; ++jj) bflyp(v[2 * jj], v[2 * jj + 1], NEG2);   // bit 1
#pragma unroll
    for (int jj = 0; jj < 8; jj += 2) {                                     // bit 11
        bflyp(v[2 * jj],     v[2 * jj + 2], NEG2);
        bflyp(v[2 * jj + 1], v[2 * jj + 3], NEG2);
    }
#pragma unroll
    for (int g = 0; g < 8; g += 4)                                          // bit 12
#pragma unroll
        for (int jj = g; jj < g + 2; ++jj) {
            bflyp(v[2 * jj],     v[2 * jj + 4], NEG2);
            bflyp(v[2 * jj + 1], v[2 * jj + 5], NEG2);
        }
#pragma unroll
    for (int jj = 0; jj < 4; ++jj) {                                        // bit 13
        bflyp(v[2 * jj],     v[2 * jj + 8], NEG2);
        bflyp(v[2 * jj + 1], v[2 * jj + 9], NEG2);
    }
    {                                                                       // bit 5
        const float sg = (lane & 8) ? -1.f : 1.f;
        const unsigned long long S = pack2(sg, sg);
#pragma unroll
        for (int i = 0; i < 16; ++i) v[i] = shflb(v[i], 8, S);
    }
#pragma unroll
    for (int jj = 0; jj < 8; ++jj) {
        float a, b, c, d;
        unpack2(v[2 * jj], a, b);
        unpack2(v[2 * jj + 1], c, d);
        *reinterpret_cast<float4*>(s + 4 * tid + 2048 * jj) = make_float4(a, b, c, d);
    }
    __syncthreads();

    // ---- Phase B: bits {6..9} + {10 pack} + {2,3,4 shfl} ----
    const int w  = tid >> 5;
    const int eA = lane + 32 * (w & 1) + 2048 * (w >> 1);
#pragma unroll
    for (int i = 0; i < 16; ++i)
        v[i] = pack2(s[eA + 64 * i], s[eA + 64 * i + 1024]);
#pragma unroll
    for (int i = 0; i < 16; i += 2) bflyp(v[i], v[i + 1], NEG2);            // bit 6
#pragma unroll
    for (int i = 0; i < 16; i += 4) {                                       // bit 7
        bflyp(v[i],     v[i + 2], NEG2);
        bflyp(v[i + 1], v[i + 3], NEG2);
    }
#pragma unroll
    for (int g = 0; g < 16; g += 8)                                         // bit 8
#pragma unroll
        for (int i = g; i < g + 4; ++i) bflyp(v[i], v[i + 4], NEG2);
#pragma unroll
    for (int i = 0; i < 8; ++i) bflyp(v[i], v[i + 8], NEG2);                // bit 9
#pragma unroll
    for (int i = 0; i < 16; ++i) v[i] = bflyin(v[i]);                       // bit 10
#pragma unroll
    for (int m = 0; m < 3; ++m) {                                           // bits 2..4
        const int mask = 4 << m;
        const float sg = (lane & mask) ? -1.f : 1.f;
        const unsigned long long S = pack2(sg, sg);
#pragma unroll
        for (int i = 0; i < 16; ++i) v[i] = shflb(v[i], mask, S);
    }
#pragma unroll
    for (int i = 0; i < 16; ++i) {
        float a, b;
        unpack2(v[i], a, b);
        y[base + eA + 64 * i]        = a;
        y[base + eA + 64 * i + 1024] = b;
    }
}

// ----------------------------------------------------------------------------
// Pass 2 (TMA, persistent, triple-buffered): bits 14..24.
// [2048 rows x 16384 cols]; stripe = 8 cols x 2048 rows = 64 KB.
// grid = #SMs; block b handles stripes b, b+grid, ...  Pipeline:
//   wait(buf k) -> issue load stripe k+1 into buf (k+1)%3 -> compute ->
//   commit store (no inline wait).  wait_group 1 before each load ensures
//   the store that used that buffer (iter k-2) has drained.
// ----------------------------------------------------------------------------
__global__ void __launch_bounds__(512, 1) wht_pass2_tma(const __grid_constant__ CUtensorMap tmap) {
    extern __shared__ __align__(16) float t[];          // 3*16384 floats + mbars
    uint64_t* mbar = reinterpret_cast<uint64_t*>(t + 3 * 16384);
    const int tid  = threadIdx.x;
    const int lane = tid & 31;
    const int c    = tid & 7;
    const unsigned long long NEG2 = pack2(-2.f, -2.f);
    const uint32_t ts = smem_u32(t);
    const uint32_t mb0 = smem_u32(mbar);

    if (tid == 0) {
#pragma unroll
        for (int j = 0; j < 3; ++j)
            asm volatile("mbarrier.init.shared.b64 [%0], %1;"
                         :: "r"(mb0 + 8 * j), "r"(1) : "memory");
    }
    __syncthreads();

    const int nstripe = 2048;
    const int stride  = gridDim.x;
    int ph0 = 0, ph1 = 0, ph2 = 0;

    // prologue: load first stripe into buf 0
    if (tid == 0 && blockIdx.x < nstripe) {
        asm volatile("mbarrier.arrive.expect_tx.shared.b64 _, [%0], %1;"
                     :: "r"(mb0), "r"(65536u) : "memory");
        const int cx = blockIdx.x * 8;
#pragma unroll
        for (int kk = 0; kk < 8; ++kk)
            asm volatile(
                "cp.async.bulk.tensor.2d.shared::cta.global.tile.mbarrier::complete_tx::bytes "
                "[%0], [%1, {%2, %3}], [%4];"
                :: "r"(ts + kk * 8192), "l"(&tmap), "r"(cx), "r"(kk * 256), "r"(mb0)
                : "memory");
    }

    int k = 0;
    for (int sIdx = blockIdx.x; sIdx < nstripe; sIdx += stride, ++k) {
        const int b = k % 3;
        const uint32_t mb = mb0 + 8 * b;
        const uint32_t tbase = ts + (uint32_t)b * 65536u;
        float* tb = t + b * 16384;

        // wait current buffer full
        int ph = (b == 0) ? ph0 : (b == 1) ? ph1 : ph2;
        mbar_wait(mb, ph);
        if (b == 0) ph0 ^= 1; else if (b == 1) ph1 ^= 1; else ph2 ^= 1;

        // issue next stripe's load into buf (k+1)%3 (overlaps compute below)
        const int snext = sIdx + stride;
        if (tid == 0 && snext < nstripe) {
            const int bn = (k + 1) % 3;
            const uint32_t mbn = mb0 + 8 * bn;
            const uint32_t tn  = ts + (uint32_t)bn * 65536u;
            // ensure the store that last used buf bn (iter k-2) has drained
            asm volatile("cp.async.bulk.wait_group 1;" ::: "memory");
            asm volatile("mbarrier.arrive.expect_tx.shared.b64 _, [%0], %1;"
                         :: "r"(mbn), "r"(65536u) : "memory");
            const int cx = snext * 8;
#pragma unroll
            for (int kk = 0; kk < 8; ++kk)
                asm volatile(
                    "cp.async.bulk.tensor.2d.shared::cta.global.tile.mbarrier::complete_tx::bytes "
                    "[%0], [%1, {%2, %3}], [%4];"
                    :: "r"(tn + kk * 8192), "l"(&tmap), "r"(cx), "r"(kk * 256), "r"(mbn)
                    : "memory");
        }

        unsigned long long v[16];

        // ---- Phase A: r = rl + 64*i (+1024 pack); row bits {6..9} + {10} ----
        const int rl = tid >> 3;
#pragma unroll
        for (int i = 0; i < 16; ++i)
            v[i] = pack2(tb[(rl + 64 * i) * 8 + c],
                         tb[(rl + 64 * (i + 16)) * 8 + c]);
#pragma unroll
        for (int i = 0; i < 16; i += 2) bflyp(v[i], v[i + 1], NEG2);        // bit 6
#pragma unroll
        for (int i = 0; i < 16; i += 4) {                                   // bit 7
            bflyp(v[i],     v[i + 2], NEG2);
            bflyp(v[i + 1], v[i + 3], NEG2);
        }
#pragma unroll
        for (int g = 0; g < 16; g += 8)                                     // bit 8
#pragma unroll
            for (int i = g; i < g + 4; ++i) bflyp(v[i], v[i + 4], NEG2);
#pragma unroll
        for (int i = 0; i < 8; ++i) bflyp(v[i], v[i + 8], NEG2);            // bit 9
#pragma unroll
        for (int i = 0; i < 16; ++i) v[i] = bflyin(v[i]);                   // bit 10
#pragma unroll
        for (int i = 0; i < 16; ++i) {
            float a, bq;
            unpack2(v[i], a, bq);
            tb[(rl + 64 * i) * 8 + c]        = a;
            tb[(rl + 64 * (i + 16)) * 8 + c] = bq;
        }
        __syncthreads();

        // ---- Phase B: r = q + 4*i (+64 pack) + 128*w; bits {2..5} + {0,1 shfl} ----
        const int q  = (lane >> 3) & 3;
        const int w  = tid >> 5;
        const int rb = q + 128 * w;
#pragma unroll
        for (int i = 0; i < 16; ++i)
            v[i] = pack2(tb[(rb + 4 * i) * 8 + c],
                         tb[(rb + 4 * (i + 16)) * 8 + c]);  // pack = bit 6 (passive)
#pragma unroll
        for (int i = 0; i < 16; i += 2) bflyp(v[i], v[i + 1], NEG2);        // bit 2
#pragma unroll
        for (int i = 0; i < 16; i += 4) {                                   // bit 3
            bflyp(v[i],     v[i + 2], NEG2);
            bflyp(v[i + 1], v[i + 3], NEG2);
        }
#pragma unroll
        for (int g = 0; g < 16; g += 8)                                     // bit 4
#pragma unroll
            for (int i = g; i < g + 4; ++i) bflyp(v[i], v[i + 4], NEG2);
#pragma unroll
        for (int i = 0; i < 8; ++i) bflyp(v[i], v[i + 8], NEG2);            // bit 5
#pragma unroll
        for (int m = 0; m < 2; ++m) {                                       // bits 0,1
            const int mask = 8 << m;
            const float sg = (lane & mask) ? -1.f : 1.f;
            const unsigned long long S = pack2(sg, sg);
#pragma unroll
            for (int i = 0; i < 16; ++i) v[i] = shflb(v[i], mask, S);
        }
#pragma unroll
        for (int i = 0; i < 16; ++i) {
            float a, bq;
            unpack2(v[i], a, bq);
            tb[(rb + 4 * i) * 8 + c]        = a;
            tb[(rb + 4 * (i + 16)) * 8 + c] = bq;
        }
        __syncthreads();

        // fire-and-forget TMA store of this stripe
        if (tid == 0) {
            asm volatile("fence.proxy.async.shared::cta;" ::: "memory");
            const int cx = sIdx * 8;
#pragma unroll
            for (int kk = 0; kk < 8; ++kk)
                asm volatile(
                    "cp.async.bulk.tensor.2d.global.shared::cta.tile.bulk_group "
                    "[%0, {%1, %2}], [%3];"
                    :: "l"(&tmap), "r"(cx), "r"(kk * 256), "r"(tbase + kk * 8192)
                    : "memory");
            asm volatile("cp.async.bulk.commit_group;" ::: "memory");
        }
        // no inline wait: next iteration's wait_group 1 gates buffer reuse
    }

    if (tid == 0)
        asm volatile("cp.async.bulk.wait_group 0;" ::: "memory");
    __syncthreads();
}

// ----------------------------------------------------------------------------
// Pass 2 (LDG fallback) - R7 kernel verbatim, known correct.
// ----------------------------------------------------------------------------
__global__ void __launch_bounds__(512, 2) wht_pass2_ldg(float* __restrict__ y) {
    extern __shared__ float t[];
    const int tid  = threadIdx.x;
    const int lane = tid & 31;
    const int c    = tid & 7;
    const int cb   = blockIdx.x * 8 + c;
    const unsigned long long NEG2 = pack2(-2.f, -2.f);

    unsigned long long v[16];

    const int rl = tid >> 3;
    {
        const float* src = y + cb + rl * 16384;
#pragma unroll
        for (int i = 0; i < 16; ++i) {
            float a = src[(64 * i) * 16384];
            float b = src[(64 * (i + 16)) * 16384];
            v[i] = pack2(a, b);
        }
    }
#pragma unroll
    for (int i = 0; i < 16; i += 2) bflyp(v[i], v[i + 1], NEG2);
#pragma unroll
    for (int i = 0; i < 16; i += 4) {
        bflyp(v[i],     v[i + 2], NEG2);
        bflyp(v[i + 1], v[i + 3], NEG2);
    }
#pragma unroll
    for (int g = 0; g < 16; g += 8)
#pragma unroll
        for (int i = g; i < g + 4; ++i) bflyp(v[i], v[i + 4], NEG2);
#pragma unroll
    for (int i = 0; i < 8; ++i) bflyp(v[i], v[i + 8], NEG2);
#pragma unroll
    for (int i = 0; i < 16; ++i) v[i] = bflyin(v[i]);
#pragma unroll
    for (int i = 0; i < 16; ++i) {
        float a, b;
        unpack2(v[i], a, b);
        t[(rl + 64 * i) * 8 + c]        = a;
        t[(rl + 64 * (i + 16)) * 8 + c] = b;
    }
    __syncthreads();

    const int q  = (lane >> 3) & 3;
    const int w  = tid >> 5;
    const int rb = q + 128 * w;
#pragma unroll
    for (int i = 0; i < 16; ++i)
        v[i] = pack2(t[(rb + 4 * i) * 8 + c],
                     t[(rb + 4 * (i + 16)) * 8 + c]);
#pragma unroll
    for (int i = 0; i < 16; i += 2) bflyp(v[i], v[i + 1], NEG2);
#pragma unroll
    for (int i = 0; i < 16; i += 4) {
        bflyp(v[i],     v[i + 2], NEG2);
        bflyp(v[i + 1], v[i + 3], NEG2);
    }
#pragma unroll
    for (int g = 0; g < 16; g += 8)
#pragma unroll
        for (int i = g; i < g + 4; ++i) bflyp(v[i], v[i + 4], NEG2);
#pragma unroll
    for (int i = 0; i < 8; ++i) bflyp(v[i], v[i + 8], NEG2);
#pragma unroll
    for (int m = 0; m < 2; ++m) {
        const int mask = 8 << m;
        const float sg = (lane & mask) ? -1.f : 1.f;
        const unsigned long long S = pack2(sg, sg);
#pragma unroll
        for (int i = 0; i < 16; ++i) v[i] = shflb(v[i], mask, S);
    }
    float* dst = y + cb;
#pragma unroll
    for (int i = 0; i < 16; ++i) {
        float a, b;
        unpack2(v[i], a, b);
        dst[(rb + 4 * i) * 16384]        = a;
        dst[(rb + 4 * (i + 16)) * 16384] = b;
    }
}

// ----------------------------------------------------------------------------
typedef CUresult (*PFN_encodeTiled)(
    CUtensorMap*, CUtensorMapDataType, cuuint32_t, void*,
    const cuuint64_t*, const cuuint64_t*, const cuuint32_t*, const cuuint32_t*,
    CUtensorMapInterleave, CUtensorMapSwizzle, CUtensorMapL2promotion,
    CUtensorMapFloatOOBfill);

extern "C" void kernel_launch(void* const* d_in, const int* in_sizes, int n_in,
                              void* d_out, int out_size) {
    (void)in_sizes; (void)n_in; (void)out_size;
    const float* x = (const float*)d_in[0];
    float* y = (float*)d_out;

    const int SMEM_P2 = 3 * 65536 + 32;   // 3 buffers + mbarriers

    cudaFuncSetAttribute(wht_pass1,     cudaFuncAttributeMaxDynamicSharedMemorySize, 65536);
    cudaFuncSetAttribute(wht_pass2_tma, cudaFuncAttributeMaxDynamicSharedMemorySize, SMEM_P2);
    cudaFuncSetAttribute(wht_pass2_ldg, cudaFuncAttributeMaxDynamicSharedMemorySize, 65536);

    // Pass 1: bits 0..13
    wht_pass1<<<2048, 512, 65536>>>(x, y);

    // Build tensor map for pass 2 (runtime-resolved driver API; no -lcuda dep)
    bool tma_ok = false;
    CUtensorMap tmap;
    {
        void* fp = nullptr;
        cudaDriverEntryPointQueryResult qr = cudaDriverEntryPointSymbolNotFound;
        if (cudaGetDriverEntryPointByVersion("cuTensorMapEncodeTiled", &fp, 12000,
                                             cudaEnableDefault, &qr) == cudaSuccess &&
            qr == cudaDriverEntryPointSuccess && fp) {
            PFN_encodeTiled enc = (PFN_encodeTiled)fp;
            cuuint64_t dims[2]    = {16384, 2048};
            cuuint64_t strides[1] = {16384ull * 4ull};
            cuuint32_t box[2]     = {8, 256};
            cuuint32_t es[2]      = {1, 1};
            tma_ok = (enc(&tmap, CU_TENSOR_MAP_DATA_TYPE_FLOAT32, 2, y,
                          dims, strides, box, es,
                          CU_TENSOR_MAP_INTERLEAVE_NONE, CU_TENSOR_MAP_SWIZZLE_NONE,
                          CU_TENSOR_MAP_L2_PROMOTION_L2_128B,
                          CU_TENSOR_MAP_FLOAT_OOB_FILL_NONE) == CUDA_SUCCESS);
        }
    }

    // Pass 2: bits 14..24
    if (tma_ok) {
        int nsm = 148;
        cudaDeviceGetAttribute(&nsm, cudaDevAttrMultiProcessorCount, 0);
        wht_pass2_tma<<<nsm, 512, SMEM_P2>>>(tmap);
    } else {
        wht_pass2_ldg<<<2048, 512, 65536>>>(y);
    }
}